// round 5
// baseline (speedup 1.0000x reference)
#include <cuda_runtime.h>
#include <cuda_bf16.h>
#include <math.h>
#include <stdint.h>

#define D     768
#define SEQ   4096
#define BATCH 4
#define NTOK  (BATCH * SEQ)
#define SCALE 0.03608439182435161f  // 1/sqrt(768)

typedef __nv_bfloat16 bf16;

// ---------------------------------------------------------------------------
// Device-global scratch
// ---------------------------------------------------------------------------
__device__ __align__(256) bf16 g_Xh[NTOK * D], g_Xl[NTOK * D];
__device__ __align__(256) bf16 g_Wh[3 * D * D], g_Wl[3 * D * D];
__device__ __align__(256) bf16 g_Qh[NTOK * D], g_Ql[NTOK * D];
__device__ __align__(256) bf16 g_Kh[NTOK * D], g_Kl[NTOK * D];
__device__ __align__(256) bf16 g_Vth[NTOK * D], g_Vtl[NTOK * D];  // [b][d][seq]
__device__ float g_S[(size_t)BATCH * SEQ * SEQ];                   // raw scaled scores
__device__ __align__(256) bf16 g_Ph[(size_t)BATCH * SEQ * SEQ];
__device__ __align__(256) bf16 g_Pl[(size_t)BATCH * SEQ * SEQ];

#define LSTR     40                     // padded bf16 stride (conflict-free ldmatrix)
#define TILE_A   (128 * LSTR * 2)       // 10240 B
#define TILE_B3  (384 * LSTR * 2)       // 30720 B
// 256-thread kernel (scores): stage = Ah|Al|Bh|Bl all 128-row
#define STAGE_S  (4 * TILE_A)           // 40960
#define DYN_S    (2 * STAGE_S)          // 81920
// 512-thread kernel (qkv/pv): A 128-row, B 384-row
#define STAGE_W  (2 * TILE_A + 2 * TILE_B3)   // 81920
#define DYN_W    (2 * STAGE_W)                 // 163840

// ---------------------------------------------------------------------------
// PTX helpers
// ---------------------------------------------------------------------------
__device__ __forceinline__ uint32_t smem_u32(const void* p) {
    uint32_t a;
    asm("{ .reg .u64 t; cvta.to.shared.u64 t, %1; cvt.u32.u64 %0, t; }" : "=r"(a) : "l"(p));
    return a;
}
__device__ __forceinline__ void ldsm4(uint32_t r[4], uint32_t addr) {
    asm volatile("ldmatrix.sync.aligned.m8n8.x4.shared.b16 {%0,%1,%2,%3}, [%4];"
                 : "=r"(r[0]), "=r"(r[1]), "=r"(r[2]), "=r"(r[3]) : "r"(addr));
}
__device__ __forceinline__ void mma16816(float c[4], const uint32_t a[4],
                                         uint32_t b0, uint32_t b1) {
    asm volatile(
        "mma.sync.aligned.m16n8k16.row.col.f32.bf16.bf16.f32 "
        "{%0,%1,%2,%3}, {%4,%5,%6,%7}, {%8,%9}, {%0,%1,%2,%3};"
        : "+f"(c[0]), "+f"(c[1]), "+f"(c[2]), "+f"(c[3])
        : "r"(a[0]), "r"(a[1]), "r"(a[2]), "r"(a[3]), "r"(b0), "r"(b1));
}
#define CP16(dst, src) asm volatile("cp.async.cg.shared.global [%0], [%1], 16;" :: "r"(dst), "l"(src) : "memory")
#define CP_COMMIT()    asm volatile("cp.async.commit_group;" ::: "memory")
#define CP_WAIT0()     asm volatile("cp.async.wait_group 0;" ::: "memory")
#define CP_WAIT1()     asm volatile("cp.async.wait_group 1;" ::: "memory")

__device__ __forceinline__ unsigned short bfu(bf16 x) {
    return *reinterpret_cast<unsigned short*>(&x);
}
__device__ __forceinline__ uint32_t split_pack(float v0, float v1, uint32_t& lo) {
    bf16 h0 = __float2bfloat16_rn(v0), h1 = __float2bfloat16_rn(v1);
    bf16 l0 = __float2bfloat16_rn(v0 - __bfloat162float(h0));
    bf16 l1 = __float2bfloat16_rn(v1 - __bfloat162float(h1));
    lo = (uint32_t)bfu(l0) | ((uint32_t)bfu(l1) << 16);
    return (uint32_t)bfu(h0) | ((uint32_t)bfu(h1) << 16);
}

// ===========================================================================
// 256-thread 128x128 GEMM core (scores)
// ===========================================================================
__device__ __forceinline__ void load_chunk_s(
    uint32_t stage,
    const bf16* __restrict__ Ah, const bf16* __restrict__ Al, int lda,
    const bf16* __restrict__ Bh, const bf16* __restrict__ Bl, int ldb, int k0)
{
    const int t   = threadIdx.x;
    const int seg = t & 3;
    const int r0  = t >> 2;
    #pragma unroll
    for (int i = 0; i < 2; i++) {
        const int row = r0 + i * 64;
        const uint32_t so = (uint32_t)(row * LSTR + seg * 8) * 2;
        const size_t ga = (size_t)row * lda + k0 + seg * 8;
        const size_t gb = (size_t)row * ldb + k0 + seg * 8;
        CP16(stage + 0 * TILE_A + so, Ah + ga);
        CP16(stage + 1 * TILE_A + so, Al + ga);
        CP16(stage + 2 * TILE_A + so, Bh + gb);
        CP16(stage + 3 * TILE_A + so, Bl + gb);
    }
}

__device__ __forceinline__ void compute_chunk_s(
    uint32_t stage, const uint32_t offA[2], const uint32_t offB[4],
    float acc[2][8][4])
{
    const uint32_t aH = stage, aL = stage + TILE_A;
    const uint32_t bH = stage + 2 * TILE_A, bL = stage + 3 * TILE_A;
    #pragma unroll
    for (int kk = 0; kk < 32; kk += 16) {
        uint32_t afh[2][4], afl[2][4];
        ldsm4(afh[0], aH + offA[0] + kk * 2);
        ldsm4(afh[1], aH + offA[1] + kk * 2);
        ldsm4(afl[0], aL + offA[0] + kk * 2);
        ldsm4(afl[1], aL + offA[1] + kk * 2);
        #pragma unroll
        for (int g = 0; g < 4; g++) {
            uint32_t bh[4], bl[4];
            ldsm4(bh, bH + offB[g] + kk * 2);
            ldsm4(bl, bL + offB[g] + kk * 2);
            #pragma unroll
            for (int mt = 0; mt < 2; mt++) {
                #pragma unroll
                for (int nt = 0; nt < 2; nt++) {
                    float* c = acc[mt][g * 2 + nt];
                    mma16816(c, afh[mt], bh[nt * 2], bh[nt * 2 + 1]);
                    mma16816(c, afh[mt], bl[nt * 2], bl[nt * 2 + 1]);
                    mma16816(c, afl[mt], bh[nt * 2], bh[nt * 2 + 1]);
                }
            }
        }
    }
}

__device__ __forceinline__ void gemm_run_s(
    const bf16* __restrict__ Ah, const bf16* __restrict__ Al, int lda,
    const bf16* __restrict__ Bh, const bf16* __restrict__ Bl, int ldb,
    int nchunks, float acc[2][8][4])
{
    extern __shared__ char dsm[];
    const uint32_t base = smem_u32(dsm);
    const int lane = threadIdx.x & 31;
    const int warp = threadIdx.x >> 5;
    const int wm = warp >> 1, wn = warp & 1;
    const int rowA = ((lane >> 3) & 1) * 8 + (lane & 7);
    const int colA = (lane >> 4) * 8;
    const int rowB = (lane >> 4) * 8 + (lane & 7);
    const int colB = ((lane >> 3) & 1) * 8;

    uint32_t offA[2], offB[4];
    #pragma unroll
    for (int mt = 0; mt < 2; mt++)
        offA[mt] = ((wm * 32 + mt * 16 + rowA) * LSTR + colA) * 2;
    #pragma unroll
    for (int g = 0; g < 4; g++)
        offB[g] = ((wn * 64 + g * 16 + rowB) * LSTR + colB) * 2;

    load_chunk_s(base, Ah, Al, lda, Bh, Bl, ldb, 0);
    CP_COMMIT();
    for (int c = 0; c < nchunks; c++) {
        if (c + 1 < nchunks) {
            load_chunk_s(base + ((c + 1) & 1) * STAGE_S, Ah, Al, lda, Bh, Bl, ldb,
                         (c + 1) * 32);
            CP_COMMIT();
            CP_WAIT1();
        } else {
            CP_WAIT0();
        }
        __syncthreads();
        compute_chunk_s(base + (c & 1) * STAGE_S, offA, offB, acc);
        __syncthreads();
    }
}

// ===========================================================================
// 512-thread 128x384 GEMM core (qkv / pv)
// ===========================================================================
__device__ __forceinline__ void load_chunk_w(
    uint32_t stage,
    const bf16* __restrict__ Ah, const bf16* __restrict__ Al, int lda,
    const bf16* __restrict__ Bh, const bf16* __restrict__ Bl, int ldb, int k0)
{
    const int t   = threadIdx.x;
    const int seg = t & 3;
    const int r0  = t >> 2;          // 0..127
    {
        const uint32_t so = (uint32_t)(r0 * LSTR + seg * 8) * 2;
        const size_t ga = (size_t)r0 * lda + k0 + seg * 8;
        CP16(stage + 0 * TILE_A + so, Ah + ga);
        CP16(stage + 1 * TILE_A + so, Al + ga);
    }
    const uint32_t bbase = stage + 2 * TILE_A;
    #pragma unroll
    for (int i = 0; i < 3; i++) {
        const int row = r0 + i * 128;
        const uint32_t so = (uint32_t)(row * LSTR + seg * 8) * 2;
        const size_t gb = (size_t)row * ldb + k0 + seg * 8;
        CP16(bbase + so,           Bh + gb);
        CP16(bbase + TILE_B3 + so, Bl + gb);
    }
}

__device__ __forceinline__ void compute_chunk_w(
    uint32_t stage, const uint32_t offA[2], const uint32_t offB[6],
    float acc[2][12][4])
{
    const uint32_t aH = stage, aL = stage + TILE_A;
    const uint32_t bH = stage + 2 * TILE_A, bL = bH + TILE_B3;
    #pragma unroll
    for (int kk = 0; kk < 32; kk += 16) {
        uint32_t afh[2][4], afl[2][4];
        ldsm4(afh[0], aH + offA[0] + kk * 2);
        ldsm4(afh[1], aH + offA[1] + kk * 2);
        ldsm4(afl[0], aL + offA[0] + kk * 2);
        ldsm4(afl[1], aL + offA[1] + kk * 2);
        #pragma unroll
        for (int g = 0; g < 6; g++) {
            uint32_t bh[4], bl[4];
            ldsm4(bh, bH + offB[g] + kk * 2);
            ldsm4(bl, bL + offB[g] + kk * 2);
            #pragma unroll
            for (int mt = 0; mt < 2; mt++) {
                #pragma unroll
                for (int nt = 0; nt < 2; nt++) {
                    float* c = acc[mt][g * 2 + nt];
                    mma16816(c, afh[mt], bh[nt * 2], bh[nt * 2 + 1]);
                    mma16816(c, afh[mt], bl[nt * 2], bl[nt * 2 + 1]);
                    mma16816(c, afl[mt], bh[nt * 2], bh[nt * 2 + 1]);
                }
            }
        }
    }
}

__device__ __forceinline__ void gemm_run_w(
    const bf16* __restrict__ Ah, const bf16* __restrict__ Al, int lda,
    const bf16* __restrict__ Bh, const bf16* __restrict__ Bl, int ldb,
    int nchunks, float acc[2][12][4])
{
    extern __shared__ char dsm[];
    const uint32_t base = smem_u32(dsm);
    const int lane = threadIdx.x & 31;
    const int warp = threadIdx.x >> 5;     // 0..15
    const int wm = warp >> 2, wn = warp & 3;   // 4x4 warp grid: 32 x 96 tiles
    const int rowA = ((lane >> 3) & 1) * 8 + (lane & 7);
    const int colA = (lane >> 4) * 8;
    const int rowB = (lane >> 4) * 8 + (lane & 7);
    const int colB = ((lane >> 3) & 1) * 8;

    uint32_t offA[2], offB[6];
    #pragma unroll
    for (int mt = 0; mt < 2; mt++)
        offA[mt] = ((wm * 32 + mt * 16 + rowA) * LSTR + colA) * 2;
    #pragma unroll
    for (int g = 0; g < 6; g++)
        offB[g] = ((wn * 96 + g * 16 + rowB) * LSTR + colB) * 2;

    load_chunk_w(base, Ah, Al, lda, Bh, Bl, ldb, 0);
    CP_COMMIT();
    for (int c = 0; c < nchunks; c++) {
        if (c + 1 < nchunks) {
            load_chunk_w(base + ((c + 1) & 1) * STAGE_W, Ah, Al, lda, Bh, Bl, ldb,
                         (c + 1) * 32);
            CP_COMMIT();
            CP_WAIT1();
        } else {
            CP_WAIT0();
        }
        __syncthreads();
        compute_chunk_w(base + (c & 1) * STAGE_W, offA, offB, acc);
        __syncthreads();
    }
}

// ===========================================================================
// Epilogues
// ===========================================================================
__device__ __forceinline__ void store_f32_s(
    float* __restrict__ C, size_t ldc, int row0, int col0,
    const float acc[2][8][4], float scale)
{
    const int lane = threadIdx.x & 31;
    const int warp = threadIdx.x >> 5;
    const int wm = warp >> 1, wn = warp & 1;
    #pragma unroll
    for (int mt = 0; mt < 2; mt++) {
        const int r = row0 + wm * 32 + mt * 16 + (lane >> 2);
        #pragma unroll
        for (int j = 0; j < 8; j++) {
            const int c = col0 + wn * 64 + j * 8 + (lane & 3) * 2;
            *(float2*)(C + (size_t)r * ldc + c) =
                make_float2(acc[mt][j][0] * scale, acc[mt][j][1] * scale);
            *(float2*)(C + (size_t)(r + 8) * ldc + c) =
                make_float2(acc[mt][j][2] * scale, acc[mt][j][3] * scale);
        }
    }
}

__device__ __forceinline__ void store_f32_w(
    float* __restrict__ C, size_t ldc, int row0, int col0,
    const float acc[2][12][4])
{
    const int lane = threadIdx.x & 31;
    const int warp = threadIdx.x >> 5;
    const int wm = warp >> 2, wn = warp & 3;
    #pragma unroll
    for (int mt = 0; mt < 2; mt++) {
        const int r = row0 + wm * 32 + mt * 16 + (lane >> 2);
        #pragma unroll
        for (int j = 0; j < 12; j++) {
            const int c = col0 + wn * 96 + j * 8 + (lane & 3) * 2;
            *(float2*)(C + (size_t)r * ldc + c) = make_float2(acc[mt][j][0], acc[mt][j][1]);
            *(float2*)(C + (size_t)(r + 8) * ldc + c) = make_float2(acc[mt][j][2], acc[mt][j][3]);
        }
    }
}

__device__ __forceinline__ void store_split_w(
    bf16* __restrict__ Hh, bf16* __restrict__ Hl, size_t ldc,
    int row0, int col0, const float acc[2][12][4])
{
    const int lane = threadIdx.x & 31;
    const int warp = threadIdx.x >> 5;
    const int wm = warp >> 2, wn = warp & 3;
    #pragma unroll
    for (int mt = 0; mt < 2; mt++) {
        const int r = row0 + wm * 32 + mt * 16 + (lane >> 2);
        #pragma unroll
        for (int j = 0; j < 12; j++) {
            const int c = col0 + wn * 96 + j * 8 + (lane & 3) * 2;
            uint32_t lo0, lo1;
            uint32_t hi0 = split_pack(acc[mt][j][0], acc[mt][j][1], lo0);
            uint32_t hi1 = split_pack(acc[mt][j][2], acc[mt][j][3], lo1);
            *(uint32_t*)(Hh + (size_t)r * ldc + c)       = hi0;
            *(uint32_t*)(Hl + (size_t)r * ldc + c)       = lo0;
            *(uint32_t*)(Hh + (size_t)(r + 8) * ldc + c) = hi1;
            *(uint32_t*)(Hl + (size_t)(r + 8) * ldc + c) = lo1;
        }
    }
}

// Transposed V store via smem, plane by plane. 128 x 384 tile.
#define VT_STR 392
__device__ __forceinline__ void store_vt_w(int row0, int col0, const float acc[2][12][4])
{
    extern __shared__ char dsm[];
    unsigned short* sp = (unsigned short*)dsm;
    const int tid  = threadIdx.x;
    const int lane = tid & 31;
    const int warp = tid >> 5;
    const int wm = warp >> 2, wn = warp & 3;

    const int b   = row0 >> 12;
    const int rin = row0 & (SEQ - 1);

    #pragma unroll
    for (int plane = 0; plane < 2; plane++) {
        __syncthreads();
        #pragma unroll
        for (int mt = 0; mt < 2; mt++) {
            const int r = wm * 32 + mt * 16 + (lane >> 2);
            #pragma unroll
            for (int j = 0; j < 12; j++) {
                const int c = wn * 96 + j * 8 + (lane & 3) * 2;
                #pragma unroll
                for (int e = 0; e < 4; e++) {
                    float v = acc[mt][j][e];
                    bf16 h = __float2bfloat16_rn(v);
                    bf16 w = plane ? __float2bfloat16_rn(v - __bfloat162float(h)) : h;
                    sp[(r + (e >> 1) * 8) * VT_STR + c + (e & 1)] = bfu(w);
                }
            }
        }
        __syncthreads();
        bf16* dst = (plane ? g_Vtl : g_Vth) + (size_t)b * D * SEQ + rin;
        for (int idx = tid; idx < 384 * 16; idx += 512) {
            const int d   = idx >> 4;
            const int seg = idx & 15;
            uint32_t w[4];
            #pragma unroll
            for (int h = 0; h < 4; h++) {
                uint32_t a0 = sp[(seg * 8 + h * 2) * VT_STR + d];
                uint32_t a1 = sp[(seg * 8 + h * 2 + 1) * VT_STR + d];
                w[h] = a0 | (a1 << 16);
            }
            *(uint4*)(dst + (size_t)(col0 + d) * SEQ + seg * 8) = make_uint4(w[0], w[1], w[2], w[3]);
        }
    }
}

// ===========================================================================
// Kernels
// ===========================================================================
__global__ void __launch_bounds__(256) split_kernel(const float* __restrict__ src,
                                                    bf16* __restrict__ h,
                                                    bf16* __restrict__ l, int n)
{
    int i = (blockIdx.x * 256 + threadIdx.x) * 4;
    if (i >= n) return;
    float4 v = *(const float4*)(src + i);
    uint32_t lo0, lo1;
    uint32_t hi0 = split_pack(v.x, v.y, lo0);
    uint32_t hi1 = split_pack(v.z, v.w, lo1);
    *(uint2*)(h + i) = make_uint2(hi0, hi1);
    *(uint2*)(l + i) = make_uint2(lo0, lo1);
}

__global__ void __launch_bounds__(512, 1) qkv_mm()
{
    const int z    = blockIdx.z;
    const int row0 = blockIdx.y * 128;
    const int col0 = blockIdx.x * 384;
    const bf16* wh = g_Wh + (size_t)z * D * D + (size_t)col0 * D;
    const bf16* wl = g_Wl + (size_t)z * D * D + (size_t)col0 * D;

    float acc[2][12][4] = {};
    gemm_run_w(g_Xh + (size_t)row0 * D, g_Xl + (size_t)row0 * D, D,
               wh, wl, D, D / 32, acc);

    if (z == 0)      store_split_w(g_Qh, g_Ql, D, row0, col0, acc);
    else if (z == 1) store_split_w(g_Kh, g_Kl, D, row0, col0, acc);
    else             store_vt_w(row0, col0, acc);
}

__global__ void __launch_bounds__(256, 2) scores_mm()
{
    const int t = blockIdx.x;
    int by = (int)((sqrtf(8.0f * t + 1.0f) - 1.0f) * 0.5f);
    while ((by + 1) * (by + 2) / 2 <= t) by++;
    while (by * (by + 1) / 2 > t) by--;
    const int bx = t - by * (by + 1) / 2;
    const int b  = blockIdx.y;
    const int row0 = by * 128, col0 = bx * 128;
    const size_t qoff = (size_t)b * SEQ * D;

    float acc[2][8][4] = {};
    gemm_run_s(g_Qh + qoff + (size_t)row0 * D, g_Ql + qoff + (size_t)row0 * D, D,
               g_Kh + qoff + (size_t)col0 * D, g_Kl + qoff + (size_t)col0 * D, D,
               D / 32, acc);
    store_f32_s(g_S + (size_t)b * SEQ * SEQ, SEQ, row0, col0, acc, SCALE);
}

// Single-pass softmax: row cached in smem.
__global__ void __launch_bounds__(256) softmax_kernel()
{
    __shared__ float srow[SEQ];
    __shared__ float red[256];
    const int q = blockIdx.x;
    const int b = blockIdx.y;
    const float* row = g_S + (size_t)b * SEQ * SEQ + (size_t)q * SEQ;
    const int len  = q + 1;
    const int wlen = ((q >> 7) + 1) << 7;
    const int tid  = threadIdx.x;

    float m = -INFINITY;
    for (int i = tid; i < len; i += 256) {
        float v = row[i];
        srow[i] = v;
        m = fmaxf(m, v);
    }
    red[tid] = m; __syncthreads();
    #pragma unroll
    for (int s = 128; s > 0; s >>= 1) {
        if (tid < s) red[tid] = fmaxf(red[tid], red[tid + s]);
        __syncthreads();
    }
    m = red[0]; __syncthreads();

    float sum = 0.0f;
    for (int i = tid; i < len; i += 256) {
        float e = __expf(srow[i] - m);
        srow[i] = e;
        sum += e;
    }
    red[tid] = sum; __syncthreads();
    #pragma unroll
    for (int s = 128; s > 0; s >>= 1) {
        if (tid < s) red[tid] += red[tid + s];
        __syncthreads();
    }
    const float inv = 1.0f / red[0];
    __syncthreads();

    bf16* ph = g_Ph + (size_t)b * SEQ * SEQ + (size_t)q * SEQ;
    bf16* pl = g_Pl + (size_t)b * SEQ * SEQ + (size_t)q * SEQ;
    for (int i = tid; i < wlen; i += 256) {
        bf16 h, l;
        if (i < len) {
            float p = srow[i] * inv;
            h = __float2bfloat16_rn(p);
            l = __float2bfloat16_rn(p - __bfloat162float(h));
        } else {
            h = __float2bfloat16_rn(0.0f);
            l = h;
        }
        ph[i] = h;
        pl[i] = l;
    }
}

__global__ void __launch_bounds__(512, 1) pv_mm(float* __restrict__ Out)
{
    const int b    = blockIdx.z;
    const int by   = (gridDim.y - 1) - blockIdx.y;   // heavy rows first
    const int row0 = by * 128;
    const int col0 = blockIdx.x * 384;
    const int nchunks = (by + 1) * 4;

    const size_t poff = (size_t)b * SEQ * SEQ + (size_t)row0 * SEQ;
    const size_t voff = (size_t)b * D * SEQ + (size_t)col0 * SEQ;

    float acc[2][12][4] = {};
    gemm_run_w(g_Ph + poff, g_Pl + poff, SEQ,
               g_Vth + voff, g_Vtl + voff, SEQ, nchunks, acc);
    store_f32_w(Out + (size_t)b * SEQ * D, D, row0, col0, acc);
}

// ---------------------------------------------------------------------------
extern "C" void kernel_launch(void* const* d_in, const int* in_sizes, int n_in,
                              void* d_out, int out_size)
{
    const float* X  = (const float*)d_in[0];
    const float* Wq = (const float*)d_in[1];
    const float* Wk = (const float*)d_in[2];
    const float* Wv = (const float*)d_in[3];
    float* Out = (float*)d_out;

    cudaFuncSetAttribute(qkv_mm,    cudaFuncAttributeMaxDynamicSharedMemorySize, DYN_W);
    cudaFuncSetAttribute(scores_mm, cudaFuncAttributeMaxDynamicSharedMemorySize, DYN_S);
    cudaFuncSetAttribute(pv_mm,     cudaFuncAttributeMaxDynamicSharedMemorySize, DYN_W);

    bf16 *xh, *xl, *wh, *wl;
    cudaGetSymbolAddress((void**)&xh, g_Xh);
    cudaGetSymbolAddress((void**)&xl, g_Xl);
    cudaGetSymbolAddress((void**)&wh, g_Wh);
    cudaGetSymbolAddress((void**)&wl, g_Wl);

    split_kernel<<<(NTOK * D) / 1024, 256>>>(X, xh, xl, NTOK * D);
    split_kernel<<<(D * D) / 1024, 256>>>(Wq, wh + 0 * D * D, wl + 0 * D * D, D * D);
    split_kernel<<<(D * D) / 1024, 256>>>(Wk, wh + 1 * D * D, wl + 1 * D * D, D * D);
    split_kernel<<<(D * D) / 1024, 256>>>(Wv, wh + 2 * D * D, wl + 2 * D * D, D * D);

    qkv_mm<<<dim3(D / 384, NTOK / 128, 3), 512, DYN_W>>>();
    scores_mm<<<dim3(528, BATCH), 256, DYN_S>>>();
    softmax_kernel<<<dim3(SEQ, BATCH), 256>>>();
    pv_mm<<<dim3(D / 384, SEQ / 128, BATCH), 512, DYN_W>>>(Out);
}

// round 6
// speedup vs baseline: 2.0359x; 2.0359x over previous
#include <cuda_runtime.h>
#include <cuda_bf16.h>
#include <cuda_fp16.h>
#include <math.h>
#include <stdint.h>

#define D     768
#define SEQ   4096
#define BATCH 4
#define NTOK  (BATCH * SEQ)
#define SCALE 0.03608439182435161f  // 1/sqrt(768)

typedef __nv_bfloat16 bf16;

// ---------------------------------------------------------------------------
// Device-global scratch
// ---------------------------------------------------------------------------
__device__ __align__(256) bf16 g_Xh[NTOK * D], g_Xl[NTOK * D];
__device__ __align__(256) bf16 g_Wh[3 * D * D], g_Wl[3 * D * D];
__device__ __align__(256) __half g_Qf[NTOK * D];
__device__ __align__(256) __half g_Kf[NTOK * D];
__device__ __align__(256) __half g_Vtf[NTOK * D];                 // [b][d][seq]
__device__ float g_S[(size_t)BATCH * SEQ * SEQ];                   // raw scaled scores
__device__ __align__(256) __half g_Pf[(size_t)BATCH * SEQ * SEQ];

// bf16x3 core (qkv): 128x32 tiles, stride 40 (80B rows, conflict-free ldmatrix)
#define LSTR     40
#define TILE_A   (128 * LSTR * 2)        // 10240 B
#define STAGE_Q  (4 * TILE_A)            // Ah|Al|Bh|Bl = 40960
#define DYN_Q    (2 * STAGE_Q)           // 81920

// fp16 core (scores/pv): 128x64 tiles, stride 72 (144B rows, conflict-free)
#define FSTR     72
#define TILE_F   (128 * FSTR * 2)        // 18432 B
#define STAGE_F  (2 * TILE_F)            // A|B = 36864
#define DYN_F    (2 * STAGE_F)           // 73728

// ---------------------------------------------------------------------------
// PTX helpers
// ---------------------------------------------------------------------------
__device__ __forceinline__ uint32_t smem_u32(const void* p) {
    uint32_t a;
    asm("{ .reg .u64 t; cvta.to.shared.u64 t, %1; cvt.u32.u64 %0, t; }" : "=r"(a) : "l"(p));
    return a;
}
__device__ __forceinline__ void ldsm4(uint32_t r[4], uint32_t addr) {
    asm volatile("ldmatrix.sync.aligned.m8n8.x4.shared.b16 {%0,%1,%2,%3}, [%4];"
                 : "=r"(r[0]), "=r"(r[1]), "=r"(r[2]), "=r"(r[3]) : "r"(addr));
}
__device__ __forceinline__ void mma_bf16(float c[4], const uint32_t a[4],
                                         uint32_t b0, uint32_t b1) {
    asm volatile(
        "mma.sync.aligned.m16n8k16.row.col.f32.bf16.bf16.f32 "
        "{%0,%1,%2,%3}, {%4,%5,%6,%7}, {%8,%9}, {%0,%1,%2,%3};"
        : "+f"(c[0]), "+f"(c[1]), "+f"(c[2]), "+f"(c[3])
        : "r"(a[0]), "r"(a[1]), "r"(a[2]), "r"(a[3]), "r"(b0), "r"(b1));
}
__device__ __forceinline__ void mma_f16(float c[4], const uint32_t a[4],
                                        uint32_t b0, uint32_t b1) {
    asm volatile(
        "mma.sync.aligned.m16n8k16.row.col.f32.f16.f16.f32 "
        "{%0,%1,%2,%3}, {%4,%5,%6,%7}, {%8,%9}, {%0,%1,%2,%3};"
        : "+f"(c[0]), "+f"(c[1]), "+f"(c[2]), "+f"(c[3])
        : "r"(a[0]), "r"(a[1]), "r"(a[2]), "r"(a[3]), "r"(b0), "r"(b1));
}
#define CP16(dst, src) asm volatile("cp.async.cg.shared.global [%0], [%1], 16;" :: "r"(dst), "l"(src) : "memory")
#define CP_COMMIT()    asm volatile("cp.async.commit_group;" ::: "memory")
#define CP_WAIT0()     asm volatile("cp.async.wait_group 0;" ::: "memory")
#define CP_WAIT1()     asm volatile("cp.async.wait_group 1;" ::: "memory")

__device__ __forceinline__ unsigned short bfu(bf16 x) {
    return *reinterpret_cast<unsigned short*>(&x);
}
__device__ __forceinline__ unsigned short hfu(__half x) {
    return *reinterpret_cast<unsigned short*>(&x);
}
__device__ __forceinline__ uint32_t split_pack(float v0, float v1, uint32_t& lo) {
    bf16 h0 = __float2bfloat16_rn(v0), h1 = __float2bfloat16_rn(v1);
    bf16 l0 = __float2bfloat16_rn(v0 - __bfloat162float(h0));
    bf16 l1 = __float2bfloat16_rn(v1 - __bfloat162float(h1));
    lo = (uint32_t)bfu(l0) | ((uint32_t)bfu(l1) << 16);
    return (uint32_t)bfu(h0) | ((uint32_t)bfu(h1) << 16);
}
__device__ __forceinline__ uint32_t pack_h2(float v0, float v1) {
    return (uint32_t)hfu(__float2half_rn(v0)) | ((uint32_t)hfu(__float2half_rn(v1)) << 16);
}

// ===========================================================================
// bf16x3 128x128 GEMM core (qkv), 256 threads, K-chunk 32
// ===========================================================================
__device__ __forceinline__ void load_chunk_q(
    uint32_t stage,
    const bf16* __restrict__ Ah, const bf16* __restrict__ Al, int lda,
    const bf16* __restrict__ Bh, const bf16* __restrict__ Bl, int ldb, int k0)
{
    const int t   = threadIdx.x;
    const int seg = t & 3;
    const int r0  = t >> 2;
    #pragma unroll
    for (int i = 0; i < 2; i++) {
        const int row = r0 + i * 64;
        const uint32_t so = (uint32_t)(row * LSTR + seg * 8) * 2;
        const size_t ga = (size_t)row * lda + k0 + seg * 8;
        const size_t gb = (size_t)row * ldb + k0 + seg * 8;
        CP16(stage + 0 * TILE_A + so, Ah + ga);
        CP16(stage + 1 * TILE_A + so, Al + ga);
        CP16(stage + 2 * TILE_A + so, Bh + gb);
        CP16(stage + 3 * TILE_A + so, Bl + gb);
    }
}

__device__ __forceinline__ void compute_chunk_q(
    uint32_t stage, const uint32_t offA[2], const uint32_t offB[4],
    float acc[2][8][4])
{
    const uint32_t aH = stage, aL = stage + TILE_A;
    const uint32_t bH = stage + 2 * TILE_A, bL = stage + 3 * TILE_A;
    #pragma unroll
    for (int kk = 0; kk < 32; kk += 16) {
        uint32_t afh[2][4], afl[2][4];
        ldsm4(afh[0], aH + offA[0] + kk * 2);
        ldsm4(afh[1], aH + offA[1] + kk * 2);
        ldsm4(afl[0], aL + offA[0] + kk * 2);
        ldsm4(afl[1], aL + offA[1] + kk * 2);
        #pragma unroll
        for (int g = 0; g < 4; g++) {
            uint32_t bh[4], bl[4];
            ldsm4(bh, bH + offB[g] + kk * 2);
            ldsm4(bl, bL + offB[g] + kk * 2);
            #pragma unroll
            for (int mt = 0; mt < 2; mt++) {
                #pragma unroll
                for (int nt = 0; nt < 2; nt++) {
                    float* c = acc[mt][g * 2 + nt];
                    mma_bf16(c, afh[mt], bh[nt * 2], bh[nt * 2 + 1]);
                    mma_bf16(c, afh[mt], bl[nt * 2], bl[nt * 2 + 1]);
                    mma_bf16(c, afl[mt], bh[nt * 2], bh[nt * 2 + 1]);
                }
            }
        }
    }
}

__device__ __forceinline__ void gemm_run_q(
    const bf16* __restrict__ Ah, const bf16* __restrict__ Al, int lda,
    const bf16* __restrict__ Bh, const bf16* __restrict__ Bl, int ldb,
    int nchunks, float acc[2][8][4])
{
    extern __shared__ char dsm[];
    const uint32_t base = smem_u32(dsm);
    const int lane = threadIdx.x & 31;
    const int warp = threadIdx.x >> 5;
    const int wm = warp >> 1, wn = warp & 1;
    const int rowA = ((lane >> 3) & 1) * 8 + (lane & 7);
    const int colA = (lane >> 4) * 8;
    const int rowB = (lane >> 4) * 8 + (lane & 7);
    const int colB = ((lane >> 3) & 1) * 8;

    uint32_t offA[2], offB[4];
    #pragma unroll
    for (int mt = 0; mt < 2; mt++)
        offA[mt] = ((wm * 32 + mt * 16 + rowA) * LSTR + colA) * 2;
    #pragma unroll
    for (int g = 0; g < 4; g++)
        offB[g] = ((wn * 64 + g * 16 + rowB) * LSTR + colB) * 2;

    load_chunk_q(base, Ah, Al, lda, Bh, Bl, ldb, 0);
    CP_COMMIT();
    for (int c = 0; c < nchunks; c++) {
        if (c + 1 < nchunks) {
            load_chunk_q(base + ((c + 1) & 1) * STAGE_Q, Ah, Al, lda, Bh, Bl, ldb,
                         (c + 1) * 32);
            CP_COMMIT();
            CP_WAIT1();
        } else {
            CP_WAIT0();
        }
        __syncthreads();
        compute_chunk_q(base + (c & 1) * STAGE_Q, offA, offB, acc);
        __syncthreads();
    }
}

// ===========================================================================
// fp16 single-mma 128x128 GEMM core (scores/pv), 256 threads, K-chunk 64
// ===========================================================================
__device__ __forceinline__ void load_chunk_f(
    uint32_t stage,
    const __half* __restrict__ A, int lda,
    const __half* __restrict__ B, int ldb, int k0)
{
    const int t   = threadIdx.x;
    const int seg = t & 7;        // 16B segment of a 128B row (64 f16)
    const int r0  = t >> 3;       // 0..31
    #pragma unroll
    for (int i = 0; i < 4; i++) {
        const int row = r0 + i * 32;
        const uint32_t so = (uint32_t)(row * FSTR + seg * 8) * 2;
        CP16(stage + so,          A + (size_t)row * lda + k0 + seg * 8);
        CP16(stage + TILE_F + so, B + (size_t)row * ldb + k0 + seg * 8);
    }
}

__device__ __forceinline__ void compute_chunk_f(
    uint32_t stage, const uint32_t offA[2], const uint32_t offB[4],
    float acc[2][8][4])
{
    const uint32_t aT = stage, bT = stage + TILE_F;
    #pragma unroll
    for (int kk = 0; kk < 64; kk += 16) {
        uint32_t af[2][4];
        ldsm4(af[0], aT + offA[0] + kk * 2);
        ldsm4(af[1], aT + offA[1] + kk * 2);
        #pragma unroll
        for (int g = 0; g < 4; g++) {
            uint32_t bf[4];
            ldsm4(bf, bT + offB[g] + kk * 2);
            #pragma unroll
            for (int mt = 0; mt < 2; mt++) {
                #pragma unroll
                for (int nt = 0; nt < 2; nt++)
                    mma_f16(acc[mt][g * 2 + nt], af[mt], bf[nt * 2], bf[nt * 2 + 1]);
            }
        }
    }
}

__device__ __forceinline__ void gemm_run_f(
    const __half* __restrict__ A, int lda,
    const __half* __restrict__ B, int ldb,
    int nchunks, float acc[2][8][4])
{
    extern __shared__ char dsm[];
    const uint32_t base = smem_u32(dsm);
    const int lane = threadIdx.x & 31;
    const int warp = threadIdx.x >> 5;
    const int wm = warp >> 1, wn = warp & 1;
    const int rowA = ((lane >> 3) & 1) * 8 + (lane & 7);
    const int colA = (lane >> 4) * 8;
    const int rowB = (lane >> 4) * 8 + (lane & 7);
    const int colB = ((lane >> 3) & 1) * 8;

    uint32_t offA[2], offB[4];
    #pragma unroll
    for (int mt = 0; mt < 2; mt++)
        offA[mt] = ((wm * 32 + mt * 16 + rowA) * FSTR + colA) * 2;
    #pragma unroll
    for (int g = 0; g < 4; g++)
        offB[g] = ((wn * 64 + g * 16 + rowB) * FSTR + colB) * 2;

    load_chunk_f(base, A, lda, B, ldb, 0);
    CP_COMMIT();
    for (int c = 0; c < nchunks; c++) {
        if (c + 1 < nchunks) {
            load_chunk_f(base + ((c + 1) & 1) * STAGE_F, A, lda, B, ldb, (c + 1) * 64);
            CP_COMMIT();
            CP_WAIT1();
        } else {
            CP_WAIT0();
        }
        __syncthreads();
        compute_chunk_f(base + (c & 1) * STAGE_F, offA, offB, acc);
        __syncthreads();
    }
}

// ===========================================================================
// Epilogues (128x128, 8-warp 2x2 layout)
// ===========================================================================
__device__ __forceinline__ void store_f32_t(
    float* __restrict__ C, size_t ldc, int row0, int col0,
    const float acc[2][8][4], float scale)
{
    const int lane = threadIdx.x & 31;
    const int warp = threadIdx.x >> 5;
    const int wm = warp >> 1, wn = warp & 1;
    #pragma unroll
    for (int mt = 0; mt < 2; mt++) {
        const int r = row0 + wm * 32 + mt * 16 + (lane >> 2);
        #pragma unroll
        for (int j = 0; j < 8; j++) {
            const int c = col0 + wn * 64 + j * 8 + (lane & 3) * 2;
            *(float2*)(C + (size_t)r * ldc + c) =
                make_float2(acc[mt][j][0] * scale, acc[mt][j][1] * scale);
            *(float2*)(C + (size_t)(r + 8) * ldc + c) =
                make_float2(acc[mt][j][2] * scale, acc[mt][j][3] * scale);
        }
    }
}

__device__ __forceinline__ void store_f16_t(
    __half* __restrict__ Cf, size_t ldc, int row0, int col0,
    const float acc[2][8][4])
{
    const int lane = threadIdx.x & 31;
    const int warp = threadIdx.x >> 5;
    const int wm = warp >> 1, wn = warp & 1;
    #pragma unroll
    for (int mt = 0; mt < 2; mt++) {
        const int r = row0 + wm * 32 + mt * 16 + (lane >> 2);
        #pragma unroll
        for (int j = 0; j < 8; j++) {
            const int c = col0 + wn * 64 + j * 8 + (lane & 3) * 2;
            *(uint32_t*)(Cf + (size_t)r * ldc + c)       = pack_h2(acc[mt][j][0], acc[mt][j][1]);
            *(uint32_t*)(Cf + (size_t)(r + 8) * ldc + c) = pack_h2(acc[mt][j][2], acc[mt][j][3]);
        }
    }
}

// Transposed fp16 V store via smem (128x128 tile)
#define VT_STRIDE 136
__device__ __forceinline__ void store_vt_f16(int row0, int col0, const float acc[2][8][4])
{
    extern __shared__ char dsm[];
    unsigned short* sp = (unsigned short*)dsm;
    const int tid  = threadIdx.x;
    const int lane = tid & 31;
    const int warp = tid >> 5;
    const int wm = warp >> 1, wn = warp & 1;

    __syncthreads();
    #pragma unroll
    for (int mt = 0; mt < 2; mt++) {
        const int r = wm * 32 + mt * 16 + (lane >> 2);
        #pragma unroll
        for (int j = 0; j < 8; j++) {
            const int c = wn * 64 + j * 8 + (lane & 3) * 2;
            #pragma unroll
            for (int e = 0; e < 4; e++)
                sp[(r + (e >> 1) * 8) * VT_STRIDE + c + (e & 1)] =
                    hfu(__float2half_rn(acc[mt][j][e]));
        }
    }
    __syncthreads();

    const int b   = row0 >> 12;
    const int rin = row0 & (SEQ - 1);
    const int d   = tid >> 1;
    const int ks  = (tid & 1) * 64;
    __half* dst = g_Vtf + (size_t)b * D * SEQ + (size_t)(col0 + d) * SEQ + rin + ks;
    #pragma unroll
    for (int g = 0; g < 8; g++) {
        uint32_t w[4];
        #pragma unroll
        for (int h = 0; h < 4; h++) {
            uint32_t a0 = sp[(ks + g * 8 + h * 2) * VT_STRIDE + d];
            uint32_t a1 = sp[(ks + g * 8 + h * 2 + 1) * VT_STRIDE + d];
            w[h] = a0 | (a1 << 16);
        }
        *(uint4*)(dst + g * 8) = make_uint4(w[0], w[1], w[2], w[3]);
    }
}

// ===========================================================================
// Kernels
// ===========================================================================
__global__ void __launch_bounds__(256) split_kernel(const float* __restrict__ src,
                                                    bf16* __restrict__ h,
                                                    bf16* __restrict__ l, int n)
{
    int i = (blockIdx.x * 256 + threadIdx.x) * 4;
    if (i >= n) return;
    float4 v = *(const float4*)(src + i);
    uint32_t lo0, lo1;
    uint32_t hi0 = split_pack(v.x, v.y, lo0);
    uint32_t hi1 = split_pack(v.z, v.w, lo1);
    *(uint2*)(h + i) = make_uint2(hi0, hi1);
    *(uint2*)(l + i) = make_uint2(lo0, lo1);
}

__global__ void __launch_bounds__(256, 2) qkv_mm()
{
    const int z    = blockIdx.z;
    const int row0 = blockIdx.y * 128;
    const int col0 = blockIdx.x * 128;
    const bf16* wh = g_Wh + (size_t)z * D * D + (size_t)col0 * D;
    const bf16* wl = g_Wl + (size_t)z * D * D + (size_t)col0 * D;

    float acc[2][8][4] = {};
    gemm_run_q(g_Xh + (size_t)row0 * D, g_Xl + (size_t)row0 * D, D,
               wh, wl, D, D / 32, acc);

    if (z == 0)      store_f16_t(g_Qf, D, row0, col0, acc);
    else if (z == 1) store_f16_t(g_Kf, D, row0, col0, acc);
    else             store_vt_f16(row0, col0, acc);
}

__global__ void __launch_bounds__(256, 2) scores_mm()
{
    const int t = blockIdx.x;
    int by = (int)((sqrtf(8.0f * t + 1.0f) - 1.0f) * 0.5f);
    while ((by + 1) * (by + 2) / 2 <= t) by++;
    while (by * (by + 1) / 2 > t) by--;
    const int bx = t - by * (by + 1) / 2;
    const int b  = blockIdx.y;
    const int row0 = by * 128, col0 = bx * 128;
    const size_t qoff = (size_t)b * SEQ * D;

    float acc[2][8][4] = {};
    gemm_run_f(g_Qf + qoff + (size_t)row0 * D, D,
               g_Kf + qoff + (size_t)col0 * D, D, D / 64, acc);
    store_f32_t(g_S + (size_t)b * SEQ * SEQ, SEQ, row0, col0, acc, SCALE);
}

// Single-pass causal softmax; writes fp16 P zero-filled to 128 boundary.
__global__ void __launch_bounds__(256) softmax_kernel()
{
    __shared__ float srow[SEQ];
    __shared__ float red[256];
    const int q = blockIdx.x;
    const int b = blockIdx.y;
    const float* row = g_S + (size_t)b * SEQ * SEQ + (size_t)q * SEQ;
    const int len  = q + 1;
    const int wlen = ((q >> 7) + 1) << 7;
    const int tid  = threadIdx.x;

    float m = -INFINITY;
    for (int i = tid; i < len; i += 256) {
        float v = row[i];
        srow[i] = v;
        m = fmaxf(m, v);
    }
    red[tid] = m; __syncthreads();
    #pragma unroll
    for (int s = 128; s > 0; s >>= 1) {
        if (tid < s) red[tid] = fmaxf(red[tid], red[tid + s]);
        __syncthreads();
    }
    m = red[0]; __syncthreads();

    float sum = 0.0f;
    for (int i = tid; i < len; i += 256) {
        float e = __expf(srow[i] - m);
        srow[i] = e;
        sum += e;
    }
    red[tid] = sum; __syncthreads();
    #pragma unroll
    for (int s = 128; s > 0; s >>= 1) {
        if (tid < s) red[tid] += red[tid + s];
        __syncthreads();
    }
    const float inv = 1.0f / red[0];
    __syncthreads();

    __half* pf = g_Pf + (size_t)b * SEQ * SEQ + (size_t)q * SEQ;
    for (int i = tid; i < wlen; i += 256)
        pf[i] = (i < len) ? __float2half_rn(srow[i] * inv) : __float2half_rn(0.0f);
}

__global__ void __launch_bounds__(256, 2) pv_mm(float* __restrict__ Out)
{
    const int b    = blockIdx.z;
    const int by   = (gridDim.y - 1) - blockIdx.y;   // heavy rows first
    const int row0 = by * 128;
    const int col0 = blockIdx.x * 128;
    const int nchunks = (by + 1) * 2;                // Klim / 64

    const size_t poff = (size_t)b * SEQ * SEQ + (size_t)row0 * SEQ;
    const size_t voff = (size_t)b * D * SEQ + (size_t)col0 * SEQ;

    float acc[2][8][4] = {};
    gemm_run_f(g_Pf + poff, SEQ, g_Vtf + voff, SEQ, nchunks, acc);
    store_f32_t(Out + (size_t)b * SEQ * D, D, row0, col0, acc, 1.0f);
}

// ---------------------------------------------------------------------------
extern "C" void kernel_launch(void* const* d_in, const int* in_sizes, int n_in,
                              void* d_out, int out_size)
{
    const float* X  = (const float*)d_in[0];
    const float* Wq = (const float*)d_in[1];
    const float* Wk = (const float*)d_in[2];
    const float* Wv = (const float*)d_in[3];
    float* Out = (float*)d_out;

    cudaFuncSetAttribute(qkv_mm,    cudaFuncAttributeMaxDynamicSharedMemorySize, DYN_Q);
    cudaFuncSetAttribute(scores_mm, cudaFuncAttributeMaxDynamicSharedMemorySize, DYN_F);
    cudaFuncSetAttribute(pv_mm,     cudaFuncAttributeMaxDynamicSharedMemorySize, DYN_F);

    bf16 *xh, *xl, *wh, *wl;
    cudaGetSymbolAddress((void**)&xh, g_Xh);
    cudaGetSymbolAddress((void**)&xl, g_Xl);
    cudaGetSymbolAddress((void**)&wh, g_Wh);
    cudaGetSymbolAddress((void**)&wl, g_Wl);

    split_kernel<<<(NTOK * D) / 1024, 256>>>(X, xh, xl, NTOK * D);
    split_kernel<<<(D * D) / 1024, 256>>>(Wq, wh + 0 * D * D, wl + 0 * D * D, D * D);
    split_kernel<<<(D * D) / 1024, 256>>>(Wk, wh + 1 * D * D, wl + 1 * D * D, D * D);
    split_kernel<<<(D * D) / 1024, 256>>>(Wv, wh + 2 * D * D, wl + 2 * D * D, D * D);

    qkv_mm<<<dim3(D / 128, NTOK / 128, 3), 256, DYN_Q>>>();
    scores_mm<<<dim3(528, BATCH), 256, DYN_F>>>();
    softmax_kernel<<<dim3(SEQ, BATCH), 256>>>();
    pv_mm<<<dim3(D / 128, SEQ / 128, BATCH), 256, DYN_F>>>(Out);
}

// round 7
// speedup vs baseline: 3.0178x; 1.4823x over previous
#include <cuda_runtime.h>
#include <cuda_fp16.h>
#include <math.h>
#include <stdint.h>

#define D     768
#define SEQ   4096
#define BATCH 4
#define NTOK  (BATCH * SEQ)
#define SCALE 0.03608439182435161f  // 1/sqrt(768)

// ---------------------------------------------------------------------------
// Device-global scratch
// ---------------------------------------------------------------------------
__device__ __align__(256) __half g_Xf[NTOK * D];
__device__ __align__(256) __half g_Wf[3 * D * D];
__device__ __align__(256) __half g_Qf[NTOK * D];
__device__ __align__(256) __half g_Kf[NTOK * D];
__device__ __align__(256) __half g_Vtf[NTOK * D];                 // [b][d][seq]
__device__ float g_S[(size_t)BATCH * SEQ * SEQ];                   // raw scaled scores
__device__ __align__(256) __half g_Pf[(size_t)BATCH * SEQ * SEQ];

// fp16 core: 128x64 tiles, stride 72 (144B rows, conflict-free ldmatrix)
#define FSTR     72
#define TILE_F   (128 * FSTR * 2)        // 18432 B
#define STAGE_F  (2 * TILE_F)            // A|B = 36864
#define DYN_F    (2 * STAGE_F)           // 73728

// ---------------------------------------------------------------------------
// PTX helpers
// ---------------------------------------------------------------------------
__device__ __forceinline__ uint32_t smem_u32(const void* p) {
    uint32_t a;
    asm("{ .reg .u64 t; cvta.to.shared.u64 t, %1; cvt.u32.u64 %0, t; }" : "=r"(a) : "l"(p));
    return a;
}
__device__ __forceinline__ void ldsm4(uint32_t r[4], uint32_t addr) {
    asm volatile("ldmatrix.sync.aligned.m8n8.x4.shared.b16 {%0,%1,%2,%3}, [%4];"
                 : "=r"(r[0]), "=r"(r[1]), "=r"(r[2]), "=r"(r[3]) : "r"(addr));
}
__device__ __forceinline__ void mma_f16(float c[4], const uint32_t a[4],
                                        uint32_t b0, uint32_t b1) {
    asm volatile(
        "mma.sync.aligned.m16n8k16.row.col.f32.f16.f16.f32 "
        "{%0,%1,%2,%3}, {%4,%5,%6,%7}, {%8,%9}, {%0,%1,%2,%3};"
        : "+f"(c[0]), "+f"(c[1]), "+f"(c[2]), "+f"(c[3])
        : "r"(a[0]), "r"(a[1]), "r"(a[2]), "r"(a[3]), "r"(b0), "r"(b1));
}
#define CP16(dst, src) asm volatile("cp.async.cg.shared.global [%0], [%1], 16;" :: "r"(dst), "l"(src) : "memory")
#define CP_COMMIT()    asm volatile("cp.async.commit_group;" ::: "memory")
#define CP_WAIT0()     asm volatile("cp.async.wait_group 0;" ::: "memory")
#define CP_WAIT1()     asm volatile("cp.async.wait_group 1;" ::: "memory")

__device__ __forceinline__ unsigned short hfu(__half x) {
    return *reinterpret_cast<unsigned short*>(&x);
}
__device__ __forceinline__ uint32_t pack_h2(float v0, float v1) {
    return (uint32_t)hfu(__float2half_rn(v0)) | ((uint32_t)hfu(__float2half_rn(v1)) << 16);
}

// ===========================================================================
// fp16 single-mma 128x128 GEMM core, 256 threads, K-chunk 64
// ===========================================================================
__device__ __forceinline__ void load_chunk_f(
    uint32_t stage,
    const __half* __restrict__ A, int lda,
    const __half* __restrict__ B, int ldb, int k0)
{
    const int t   = threadIdx.x;
    const int seg = t & 7;        // 16B segment of a 128B row (64 f16)
    const int r0  = t >> 3;       // 0..31
    #pragma unroll
    for (int i = 0; i < 4; i++) {
        const int row = r0 + i * 32;
        const uint32_t so = (uint32_t)(row * FSTR + seg * 8) * 2;
        CP16(stage + so,          A + (size_t)row * lda + k0 + seg * 8);
        CP16(stage + TILE_F + so, B + (size_t)row * ldb + k0 + seg * 8);
    }
}

__device__ __forceinline__ void compute_chunk_f(
    uint32_t stage, const uint32_t offA[2], const uint32_t offB[4],
    float acc[2][8][4])
{
    const uint32_t aT = stage, bT = stage + TILE_F;
    #pragma unroll
    for (int kk = 0; kk < 64; kk += 16) {
        uint32_t af[2][4];
        ldsm4(af[0], aT + offA[0] + kk * 2);
        ldsm4(af[1], aT + offA[1] + kk * 2);
        #pragma unroll
        for (int g = 0; g < 4; g++) {
            uint32_t bf[4];
            ldsm4(bf, bT + offB[g] + kk * 2);
            #pragma unroll
            for (int mt = 0; mt < 2; mt++) {
                #pragma unroll
                for (int nt = 0; nt < 2; nt++)
                    mma_f16(acc[mt][g * 2 + nt], af[mt], bf[nt * 2], bf[nt * 2 + 1]);
            }
        }
    }
}

__device__ __forceinline__ void gemm_run_f(
    const __half* __restrict__ A, int lda,
    const __half* __restrict__ B, int ldb,
    int nchunks, float acc[2][8][4])
{
    extern __shared__ char dsm[];
    const uint32_t base = smem_u32(dsm);
    const int lane = threadIdx.x & 31;
    const int warp = threadIdx.x >> 5;
    const int wm = warp >> 1, wn = warp & 1;
    const int rowA = ((lane >> 3) & 1) * 8 + (lane & 7);
    const int colA = (lane >> 4) * 8;
    const int rowB = (lane >> 4) * 8 + (lane & 7);
    const int colB = ((lane >> 3) & 1) * 8;

    uint32_t offA[2], offB[4];
    #pragma unroll
    for (int mt = 0; mt < 2; mt++)
        offA[mt] = ((wm * 32 + mt * 16 + rowA) * FSTR + colA) * 2;
    #pragma unroll
    for (int g = 0; g < 4; g++)
        offB[g] = ((wn * 64 + g * 16 + rowB) * FSTR + colB) * 2;

    load_chunk_f(base, A, lda, B, ldb, 0);
    CP_COMMIT();
    for (int c = 0; c < nchunks; c++) {
        if (c + 1 < nchunks) {
            load_chunk_f(base + ((c + 1) & 1) * STAGE_F, A, lda, B, ldb, (c + 1) * 64);
            CP_COMMIT();
            CP_WAIT1();
        } else {
            CP_WAIT0();
        }
        __syncthreads();
        compute_chunk_f(base + (c & 1) * STAGE_F, offA, offB, acc);
        __syncthreads();
    }
}

// ===========================================================================
// Epilogues (128x128, 8-warp 2x2 layout)
// ===========================================================================
__device__ __forceinline__ void store_f32_t(
    float* __restrict__ C, size_t ldc, int row0, int col0,
    const float acc[2][8][4], float scale)
{
    const int lane = threadIdx.x & 31;
    const int warp = threadIdx.x >> 5;
    const int wm = warp >> 1, wn = warp & 1;
    #pragma unroll
    for (int mt = 0; mt < 2; mt++) {
        const int r = row0 + wm * 32 + mt * 16 + (lane >> 2);
        #pragma unroll
        for (int j = 0; j < 8; j++) {
            const int c = col0 + wn * 64 + j * 8 + (lane & 3) * 2;
            *(float2*)(C + (size_t)r * ldc + c) =
                make_float2(acc[mt][j][0] * scale, acc[mt][j][1] * scale);
            *(float2*)(C + (size_t)(r + 8) * ldc + c) =
                make_float2(acc[mt][j][2] * scale, acc[mt][j][3] * scale);
        }
    }
}

__device__ __forceinline__ void store_f16_t(
    __half* __restrict__ Cf, size_t ldc, int row0, int col0,
    const float acc[2][8][4])
{
    const int lane = threadIdx.x & 31;
    const int warp = threadIdx.x >> 5;
    const int wm = warp >> 1, wn = warp & 1;
    #pragma unroll
    for (int mt = 0; mt < 2; mt++) {
        const int r = row0 + wm * 32 + mt * 16 + (lane >> 2);
        #pragma unroll
        for (int j = 0; j < 8; j++) {
            const int c = col0 + wn * 64 + j * 8 + (lane & 3) * 2;
            *(uint32_t*)(Cf + (size_t)r * ldc + c)       = pack_h2(acc[mt][j][0], acc[mt][j][1]);
            *(uint32_t*)(Cf + (size_t)(r + 8) * ldc + c) = pack_h2(acc[mt][j][2], acc[mt][j][3]);
        }
    }
}

// Transposed fp16 V store via smem (128x128 tile)
#define VT_STRIDE 136
__device__ __forceinline__ void store_vt_f16(int row0, int col0, const float acc[2][8][4])
{
    extern __shared__ char dsm[];
    unsigned short* sp = (unsigned short*)dsm;
    const int tid  = threadIdx.x;
    const int lane = tid & 31;
    const int warp = tid >> 5;
    const int wm = warp >> 1, wn = warp & 1;

    __syncthreads();
    #pragma unroll
    for (int mt = 0; mt < 2; mt++) {
        const int r = wm * 32 + mt * 16 + (lane >> 2);
        #pragma unroll
        for (int j = 0; j < 8; j++) {
            const int c = wn * 64 + j * 8 + (lane & 3) * 2;
            #pragma unroll
            for (int e = 0; e < 4; e++)
                sp[(r + (e >> 1) * 8) * VT_STRIDE + c + (e & 1)] =
                    hfu(__float2half_rn(acc[mt][j][e]));
        }
    }
    __syncthreads();

    const int b   = row0 >> 12;
    const int rin = row0 & (SEQ - 1);
    const int d   = tid >> 1;
    const int ks  = (tid & 1) * 64;
    __half* dst = g_Vtf + (size_t)b * D * SEQ + (size_t)(col0 + d) * SEQ + rin + ks;
    #pragma unroll
    for (int g = 0; g < 8; g++) {
        uint32_t w[4];
        #pragma unroll
        for (int h = 0; h < 4; h++) {
            uint32_t a0 = sp[(ks + g * 8 + h * 2) * VT_STRIDE + d];
            uint32_t a1 = sp[(ks + g * 8 + h * 2 + 1) * VT_STRIDE + d];
            w[h] = a0 | (a1 << 16);
        }
        *(uint4*)(dst + g * 8) = make_uint4(w[0], w[1], w[2], w[3]);
    }
}

// ===========================================================================
// Kernels
// ===========================================================================
__global__ void __launch_bounds__(256) cvt_kernel(const float* __restrict__ src,
                                                  __half* __restrict__ dst, int n)
{
    int i = (blockIdx.x * 256 + threadIdx.x) * 8;
    if (i >= n) return;
    float4 v0 = *(const float4*)(src + i);
    float4 v1 = *(const float4*)(src + i + 4);
    *(uint4*)(dst + i) = make_uint4(pack_h2(v0.x, v0.y), pack_h2(v0.z, v0.w),
                                    pack_h2(v1.x, v1.y), pack_h2(v1.z, v1.w));
}

__global__ void __launch_bounds__(256, 2) qkv_mm()
{
    const int z    = blockIdx.z;
    const int row0 = blockIdx.y * 128;
    const int col0 = blockIdx.x * 128;

    float acc[2][8][4] = {};
    gemm_run_f(g_Xf + (size_t)row0 * D, D,
               g_Wf + (size_t)z * D * D + (size_t)col0 * D, D, D / 64, acc);

    if (z == 0)      store_f16_t(g_Qf, D, row0, col0, acc);
    else if (z == 1) store_f16_t(g_Kf, D, row0, col0, acc);
    else             store_vt_f16(row0, col0, acc);
}

__global__ void __launch_bounds__(256, 2) scores_mm()
{
    const int t = blockIdx.x;
    int by = (int)((sqrtf(8.0f * t + 1.0f) - 1.0f) * 0.5f);
    while ((by + 1) * (by + 2) / 2 <= t) by++;
    while (by * (by + 1) / 2 > t) by--;
    const int bx = t - by * (by + 1) / 2;
    const int b  = blockIdx.y;
    const int row0 = by * 128, col0 = bx * 128;
    const size_t qoff = (size_t)b * SEQ * D;

    float acc[2][8][4] = {};
    gemm_run_f(g_Qf + qoff + (size_t)row0 * D, D,
               g_Kf + qoff + (size_t)col0 * D, D, D / 64, acc);
    store_f32_t(g_S + (size_t)b * SEQ * SEQ, SEQ, row0, col0, acc, SCALE);
}

// Single-pass causal softmax; writes fp16 P zero-filled to 128 boundary.
__global__ void __launch_bounds__(256) softmax_kernel()
{
    __shared__ float srow[SEQ];
    __shared__ float red[256];
    const int q = blockIdx.x;
    const int b = blockIdx.y;
    const float* row = g_S + (size_t)b * SEQ * SEQ + (size_t)q * SEQ;
    const int len  = q + 1;
    const int wlen = ((q >> 7) + 1) << 7;
    const int tid  = threadIdx.x;

    float m = -INFINITY;
    for (int i = tid; i < len; i += 256) {
        float v = row[i];
        srow[i] = v;
        m = fmaxf(m, v);
    }
    red[tid] = m; __syncthreads();
    #pragma unroll
    for (int s = 128; s > 0; s >>= 1) {
        if (tid < s) red[tid] = fmaxf(red[tid], red[tid + s]);
        __syncthreads();
    }
    m = red[0]; __syncthreads();

    float sum = 0.0f;
    for (int i = tid; i < len; i += 256) {
        float e = __expf(srow[i] - m);
        srow[i] = e;
        sum += e;
    }
    red[tid] = sum; __syncthreads();
    #pragma unroll
    for (int s = 128; s > 0; s >>= 1) {
        if (tid < s) red[tid] += red[tid + s];
        __syncthreads();
    }
    const float inv = 1.0f / red[0];
    __syncthreads();

    __half* pf = g_Pf + (size_t)b * SEQ * SEQ + (size_t)q * SEQ;
    for (int i = tid; i < wlen; i += 256)
        pf[i] = (i < len) ? __float2half_rn(srow[i] * inv) : __float2half_rn(0.0f);
}

__global__ void __launch_bounds__(256, 2) pv_mm(float* __restrict__ Out)
{
    const int b    = blockIdx.z;
    const int by   = (gridDim.y - 1) - blockIdx.y;   // heavy rows first
    const int row0 = by * 128;
    const int col0 = blockIdx.x * 128;
    const int nchunks = (by + 1) * 2;                // Klim / 64

    const size_t poff = (size_t)b * SEQ * SEQ + (size_t)row0 * SEQ;
    const size_t voff = (size_t)b * D * SEQ + (size_t)col0 * SEQ;

    float acc[2][8][4] = {};
    gemm_run_f(g_Pf + poff, SEQ, g_Vtf + voff, SEQ, nchunks, acc);
    store_f32_t(Out + (size_t)b * SEQ * D, D, row0, col0, acc, 1.0f);
}

// ---------------------------------------------------------------------------
extern "C" void kernel_launch(void* const* d_in, const int* in_sizes, int n_in,
                              void* d_out, int out_size)
{
    const float* X  = (const float*)d_in[0];
    const float* Wq = (const float*)d_in[1];
    const float* Wk = (const float*)d_in[2];
    const float* Wv = (const float*)d_in[3];
    float* Out = (float*)d_out;

    cudaFuncSetAttribute(qkv_mm,    cudaFuncAttributeMaxDynamicSharedMemorySize, DYN_F);
    cudaFuncSetAttribute(scores_mm, cudaFuncAttributeMaxDynamicSharedMemorySize, DYN_F);
    cudaFuncSetAttribute(pv_mm,     cudaFuncAttributeMaxDynamicSharedMemorySize, DYN_F);

    __half *xf, *wf;
    cudaGetSymbolAddress((void**)&xf, g_Xf);
    cudaGetSymbolAddress((void**)&wf, g_Wf);

    cvt_kernel<<<(NTOK * D) / 2048, 256>>>(X, xf, NTOK * D);
    cvt_kernel<<<(D * D) / 2048, 256>>>(Wq, wf + 0 * D * D, D * D);
    cvt_kernel<<<(D * D) / 2048, 256>>>(Wk, wf + 1 * D * D, D * D);
    cvt_kernel<<<(D * D) / 2048, 256>>>(Wv, wf + 2 * D * D, D * D);

    qkv_mm<<<dim3(D / 128, NTOK / 128, 3), 256, DYN_F>>>();
    scores_mm<<<dim3(528, BATCH), 256, DYN_F>>>();
    softmax_kernel<<<dim3(SEQ, BATCH), 256>>>();
    pv_mm<<<dim3(D / 128, SEQ / 128, BATCH), 256, DYN_F>>>(Out);
}